// round 5
// baseline (speedup 1.0000x reference)
#include <cuda_runtime.h>
#include <cuda_bf16.h>
#include <math.h>

// QuantumLayer as a multilinear polynomial (exact identity):
//   out_o(x) = T[o] . (1,cos x0,sin x0) x ... x (1,cos x3,sin x3)
// T (4 x 3^4, batch-constant) = circuit sampled at {0,pi/2,pi}^4, inverse 3x3
// Vandermonde per axis. SINGLE fused kernel: block 0 builds T and raises a flag;
// other blocks overlap their x-loads/sincos with the build, then spin briefly.
// Hot path: 4 sincos + 320 FMA/element (measured at 85% of the FFMA-3reg cap).

__device__ __align__(16) float g_T[432];  // [o][k0][k1][k2][k3 padded to 4]
__device__ int g_flag;                    // zero-init; reset by last block each run
__device__ unsigned int g_done;

__global__ __launch_bounds__(256, 4) void qlayer_fused(
    const float* __restrict__ x, const float* __restrict__ w,
    float* __restrict__ out, int B)
{
    __shared__ __align__(16) float sh[648];   // build: bufA/bufB ; run: T as float4[108]
    __shared__ float wc[12], wsn[12];
    const int t = threadIdx.x;

    // ---------------- Block 0: build T ----------------
    if (blockIdx.x == 0) {
        if (t < 12) {
            float s, c; __sincosf(0.5f * w[t], &s, &c);
            wc[t] = c; wsn[t] = s;
        }
        __syncthreads();

        if (t < 81) {
            // half-angle cos/sin of sample angles {0, pi/2, pi}
            const float hc[3] = {1.0f, 0.70710678118654752f, 0.0f};
            const float hs[3] = {0.0f, 0.70710678118654752f, 1.0f};
            const int a[4] = {t / 27, (t / 9) % 3, (t / 3) % 3, t % 3};

            float vr[16], vi[16];
#pragma unroll
            for (int i = 0; i < 16; i++) { vr[i] = 0.0f; vi[i] = 0.0f; }
            vr[0] = 1.0f;

#pragma unroll
            for (int q = 0; q < 4; q++) {            // RX(x_q) at sample angles
                const float cq = hc[a[q]], sq = hs[a[q]];
                const int bit = 1 << (3 - q);
#pragma unroll
                for (int i = 0; i < 16; i++) {
                    if (i & bit) continue;
                    const int i1 = i | bit;
                    float ar = vr[i], ai = vi[i], br = vr[i1], bi = vi[i1];
                    vr[i]  = cq * ar + sq * bi;  vi[i]  = cq * ai - sq * br;
                    vr[i1] = cq * br + sq * ai;  vi[i1] = cq * bi - sq * ar;
                }
            }
#pragma unroll
            for (int l = 0; l < 3; l++) {            // weight layers + CNOT ring
#pragma unroll
                for (int q = 0; q < 4; q++) {
                    const float cq = wc[l * 4 + q], sq = wsn[l * 4 + q];
                    const int bit = 1 << (3 - q);
#pragma unroll
                    for (int i = 0; i < 16; i++) {
                        if (i & bit) continue;
                        const int i1 = i | bit;
                        float ar = vr[i], ai = vi[i], br = vr[i1], bi = vi[i1];
                        vr[i]  = cq * ar + sq * bi;  vi[i]  = cq * ai - sq * br;
                        vr[i1] = cq * br + sq * ai;  vi[i1] = cq * bi - sq * ar;
                    }
                }
#pragma unroll
                for (int q = 0; q < 4; q++) {
                    const int pcb = 3 - q, ptb = 3 - ((q + 1) & 3);
#pragma unroll
                    for (int i = 0; i < 16; i++) {
                        if (((i >> pcb) & 1) == 0) continue;
                        if ((i >> ptb) & 1) continue;
                        const int i2 = i | (1 << ptb);
                        float tr = vr[i], ti = vi[i];
                        vr[i] = vr[i2]; vi[i] = vi[i2];
                        vr[i2] = tr;    vi[i2] = ti;
                    }
                }
            }

            float p[16];
#pragma unroll
            for (int i = 0; i < 16; i++) p[i] = vr[i] * vr[i] + vi[i] * vi[i];
#pragma unroll
            for (int q = 0; q < 4; q++) {
                float s = 0.0f;
#pragma unroll
                for (int i = 0; i < 16; i++)
                    s += ((i >> (3 - q)) & 1) ? -p[i] : p[i];
                sh[q * 81 + t] = s;
            }
        }
        __syncthreads();

        // Inverse Vandermonde along each axis (samples {0,pi/2,pi}, basis (1,cos,sin)):
        //   c0=(s0+s2)/2 ; c1=(s0-s2)/2 ; c2=s1-(s0+s2)/2
        const float Vi[3][3] = {{0.5f, 0.0f, 0.5f},
                                {0.5f, 0.0f, -0.5f},
                                {-0.5f, 1.0f, -0.5f}};
        const int WST[4] = {27, 9, 3, 1};
        float* src = sh;        // [0..323]
        float* dst = sh + 324;  // [324..647]
        for (int ax = 3; ax >= 0; ax--) {
            for (int e2 = t; e2 < 324; e2 += 256) {
                const int o = e2 / 81, e = e2 % 81;
                const int ws2 = WST[ax];
                const int k = (e / ws2) % 3;
                const int eb = e - k * ws2;
                const float* s = src + o * 81;
                dst[e2] = Vi[k][0] * s[eb] + Vi[k][1] * s[eb + ws2] + Vi[k][2] * s[eb + 2 * ws2];
            }
            __syncthreads();
            float* tmp = src; src = dst; dst = tmp;
        }
        // 4 passes -> result back in sh[0..323]
        for (int e2 = t; e2 < 432; e2 += 256) {
            const int o = e2 / 108, r = e2 % 108, k012 = r / 4, c = r % 4;
            g_T[e2] = (c < 3) ? src[o * 81 + k012 * 3 + c] : 0.0f;
        }
        __threadfence();
        __syncthreads();
        if (t == 0) *((volatile int*)&g_flag) = 1;
    }

    // ---------------- All blocks: per-element work ----------------
    const long long e0 = ((long long)blockIdx.x * 256 + t) * 2;
    const bool active = (e0 < B);

    float C[2][4], S[2][4];
    if (active) {
        const float4* __restrict__ x4 = (const float4*)x;
#pragma unroll
        for (int el = 0; el < 2; el++) {
            long long ei = e0 + el; if (ei >= B) ei = B - 1;
            float4 v = x4[ei];
            __sincosf(v.x, &S[el][0], &C[el][0]);
            __sincosf(v.y, &S[el][1], &C[el][1]);
            __sincosf(v.z, &S[el][2], &C[el][2]);
            __sincosf(v.w, &S[el][3], &C[el][3]);
        }
    }

    // Wait for T (block 0 already has flag=1 by construction).
    if (blockIdx.x != 0) {
        if (t == 0) {
            while (*((volatile int*)&g_flag) == 0) { __nanosleep(64); }
        }
    }
    __syncthreads();
    __threadfence();  // acquire: order T reads after flag observation

    // Load T into shared (L2 path, bypass possibly-unwarmed L1 semantics).
    float4* shT = (float4*)sh;
    if (t < 108) shT[t] = __ldcg(((const float4*)g_T) + t);
    __syncthreads();

    if (active) {
        float outv[2][4];
#pragma unroll
        for (int o = 0; o < 4; o++) {
            float acc[2];
#pragma unroll
            for (int k0 = 0; k0 < 3; k0++) {
                float Aacc[2];
#pragma unroll
                for (int k1 = 0; k1 < 3; k1++) {
                    float Bacc[2];
#pragma unroll
                    for (int k2 = 0; k2 < 3; k2++) {
                        const float4 tq = shT[o * 27 + k0 * 9 + k1 * 3 + k2];
#pragma unroll
                        for (int el = 0; el < 2; el++) {
                            float D = fmaf(tq.z, S[el][3], fmaf(tq.y, C[el][3], tq.x));
                            if (k2 == 0)      Bacc[el] = D;
                            else if (k2 == 1) Bacc[el] = fmaf(C[el][2], D, Bacc[el]);
                            else              Bacc[el] = fmaf(S[el][2], D, Bacc[el]);
                        }
                    }
#pragma unroll
                    for (int el = 0; el < 2; el++) {
                        if (k1 == 0)      Aacc[el] = Bacc[el];
                        else if (k1 == 1) Aacc[el] = fmaf(C[el][1], Bacc[el], Aacc[el]);
                        else              Aacc[el] = fmaf(S[el][1], Bacc[el], Aacc[el]);
                    }
                }
#pragma unroll
                for (int el = 0; el < 2; el++) {
                    if (k0 == 0)      acc[el] = Aacc[el];
                    else if (k0 == 1) acc[el] = fmaf(C[el][0], Aacc[el], acc[el]);
                    else              acc[el] = fmaf(S[el][0], Aacc[el], acc[el]);
                }
            }
#pragma unroll
            for (int el = 0; el < 2; el++) outv[el][o] = acc[el];
        }

        float4* __restrict__ o4 = (float4*)out;
#pragma unroll
        for (int el = 0; el < 2; el++) {
            long long ei = e0 + el;
            if (ei < B) o4[ei] = make_float4(outv[el][0], outv[el][1], outv[el][2], outv[el][3]);
        }
    }

    // ---------------- Cleanup for graph replay: last block resets state ----------------
    __syncthreads();
    if (t == 0) {
        __threadfence();
        unsigned int v = atomicAdd(&g_done, 1u);
        if (v == gridDim.x - 1) {
            g_done = 0u;
            *((volatile int*)&g_flag) = 0;
        }
    }
}

// ---------------------------------------------------------------------------
extern "C" void kernel_launch(void* const* d_in, const int* in_sizes, int n_in,
                              void* d_out, int out_size) {
    const float* xp = (const float*)d_in[0];
    const float* wp = (const float*)d_in[1];
    int sx = in_sizes[0];
    if (n_in >= 2 && in_sizes[0] == 12 && in_sizes[1] != 12) {
        xp = (const float*)d_in[1];
        wp = (const float*)d_in[0];
        sx = in_sizes[1];
    }
    const int B = sx / 4;

    const int elems_per_block = 256 * 2;
    const int grid = (B + elems_per_block - 1) / elems_per_block;
    qlayer_fused<<<grid, 256>>>(xp, wp, (float*)d_out, B);
}

// round 6
// speedup vs baseline: 1.1618x; 1.1618x over previous
#include <cuda_runtime.h>
#include <cuda_bf16.h>
#include <math.h>

// QuantumLayer as a multilinear polynomial (exact identity):
//   out_o(x) = T[o] . (1,cos x0,sin x0) x ... x (1,cos x3,sin x3)
// T (4 x 3^4, batch-constant) = circuit sampled at {0,pi/2,pi}^4 + inverse 3x3
// Vandermonde per axis. Two kernels linked by PDL: build_T triggers launch
// completion right after its T stores; qlayer overlaps its x-load/sincos prolog
// with build_T and gates the T read on cudaGridDependencySynchronize().
// Hot path: 4 sincos + 320 FMA/element (85% of the FFMA-3reg structural cap).

__device__ __align__(16) float g_T[432];  // [o][k0][k1][k2][k3 padded to 4]

// ---------------------------------------------------------------------------
// Kernel 1: build T from weights (12 floats). One block, 512 threads.
// ---------------------------------------------------------------------------
__global__ void build_T_kernel(const float* __restrict__ w) {
    __shared__ float bufA[324], bufB[324];
    __shared__ float wc[12], ws[12];
    const int t = threadIdx.x;

    if (t < 12) {
        float s, c;
        __sincosf(0.5f * w[t], &s, &c);
        wc[t] = c; ws[t] = s;
    }
    __syncthreads();

    if (t < 81) {
        // half-angle cos/sin of sample angles {0, pi/2, pi}
        const float hc[3] = {1.0f, 0.70710678118654752f, 0.0f};
        const float hs[3] = {0.0f, 0.70710678118654752f, 1.0f};
        const int a[4] = {t / 27, (t / 9) % 3, (t / 3) % 3, t % 3};

        float vr[16], vi[16];
#pragma unroll
        for (int i = 0; i < 16; i++) { vr[i] = 0.0f; vi[i] = 0.0f; }
        vr[0] = 1.0f;

        // Initial RX(x_q) at sample angles (qubit q <-> bit 3-q).
#pragma unroll
        for (int q = 0; q < 4; q++) {
            const float cq = hc[a[q]], sq = hs[a[q]];
            const int bit = 1 << (3 - q);
#pragma unroll
            for (int i = 0; i < 16; i++) {
                if (i & bit) continue;
                const int i1 = i | bit;
                float ar = vr[i], ai = vi[i], br = vr[i1], bi = vi[i1];
                vr[i]  = cq * ar + sq * bi;  vi[i]  = cq * ai - sq * br;
                vr[i1] = cq * br + sq * ai;  vi[i1] = cq * bi - sq * ar;
            }
        }
        // 3 layers: RX(w) x4 then CNOT ring.
#pragma unroll
        for (int l = 0; l < 3; l++) {
#pragma unroll
            for (int q = 0; q < 4; q++) {
                const float cq = wc[l * 4 + q], sq = ws[l * 4 + q];
                const int bit = 1 << (3 - q);
#pragma unroll
                for (int i = 0; i < 16; i++) {
                    if (i & bit) continue;
                    const int i1 = i | bit;
                    float ar = vr[i], ai = vi[i], br = vr[i1], bi = vi[i1];
                    vr[i]  = cq * ar + sq * bi;  vi[i]  = cq * ai - sq * br;
                    vr[i1] = cq * br + sq * ai;  vi[i1] = cq * bi - sq * ar;
                }
            }
#pragma unroll
            for (int q = 0; q < 4; q++) {
                const int pcb = 3 - q;
                const int ptb = 3 - ((q + 1) & 3);
#pragma unroll
                for (int i = 0; i < 16; i++) {
                    if (((i >> pcb) & 1) == 0) continue;
                    if ((i >> ptb) & 1) continue;
                    const int i2 = i | (1 << ptb);
                    float tr = vr[i], ti = vi[i];
                    vr[i] = vr[i2]; vi[i] = vi[i2];
                    vr[i2] = tr;    vi[i2] = ti;
                }
            }
        }

        float p[16];
#pragma unroll
        for (int i = 0; i < 16; i++) p[i] = vr[i] * vr[i] + vi[i] * vi[i];
#pragma unroll
        for (int q = 0; q < 4; q++) {
            float s = 0.0f;
#pragma unroll
            for (int i = 0; i < 16; i++)
                s += ((i >> (3 - q)) & 1) ? -p[i] : p[i];
            bufA[q * 81 + t] = s;
        }
    }
    __syncthreads();

    // Inverse Vandermonde for basis (1, cos, sin) at samples {0, pi/2, pi}:
    //   c0 = (s0+s2)/2 ; c1 = (s0-s2)/2 ; c2 = s1 - (s0+s2)/2
    const float Vi[3][3] = {{0.5f, 0.0f, 0.5f},
                            {0.5f, 0.0f, -0.5f},
                            {-0.5f, 1.0f, -0.5f}};
    const int WST[4] = {27, 9, 3, 1};
    float* src = bufA;
    float* dst = bufB;
    for (int ax = 3; ax >= 0; ax--) {
        if (t < 324) {
            const int o = t / 81, e = t % 81;
            const int ws2 = WST[ax];
            const int k = (e / ws2) % 3;
            const int eb = e - k * ws2;
            const float* s = src + o * 81;
            dst[t] = Vi[k][0] * s[eb] + Vi[k][1] * s[eb + ws2] + Vi[k][2] * s[eb + 2 * ws2];
        }
        __syncthreads();
        float* tmp = src; src = dst; dst = tmp;
    }

    if (t < 432) {
        const int o = t / 108, r = t % 108, k012 = r / 4, c = r % 4;
        g_T[t] = (c < 3) ? src[o * 81 + k012 * 3 + c] : 0.0f;
    }

    // Make T visible, then allow the PDL secondary to proceed ASAP.
    __threadfence();
    __syncthreads();
    cudaTriggerProgrammaticLaunchCompletion();
}

// ---------------------------------------------------------------------------
// Kernel 2: 2 elements/thread, PDL-gated T read. 320 FMA/element Horner.
// ---------------------------------------------------------------------------
__global__ __launch_bounds__(256, 4) void qlayer_kernel(
    const float* __restrict__ x, float* __restrict__ out, int B)
{
    __shared__ __align__(16) float4 shT[108];   // [o*27 + k0*9 + k1*3 + k2], .xyz = k3
    const int t = threadIdx.x;

    const long long e0 = ((long long)blockIdx.x * 256 + t) * 2;
    const bool active = (e0 < B);

    // Prolog (independent of T): overlaps with build_T under PDL.
    float C[2][4], S[2][4];
    if (active) {
        const float4* __restrict__ x4 = (const float4*)x;
#pragma unroll
        for (int el = 0; el < 2; el++) {
            long long ei = e0 + el; if (ei >= B) ei = B - 1;
            float4 v = x4[ei];
            __sincosf(v.x, &S[el][0], &C[el][0]);
            __sincosf(v.y, &S[el][1], &C[el][1]);
            __sincosf(v.z, &S[el][2], &C[el][2]);
            __sincosf(v.w, &S[el][3], &C[el][3]);
        }
    }

    // Wait for build_T's memory to be visible (no-op if not PDL-launched).
    cudaGridDependencySynchronize();

    if (t < 108) shT[t] = __ldcg(((const float4*)g_T) + t);
    __syncthreads();

    if (active) {
        float outv[2][4];  // [el][o]
#pragma unroll
        for (int o = 0; o < 4; o++) {
            float acc[2];
#pragma unroll
            for (int k0 = 0; k0 < 3; k0++) {
                float Aacc[2];
#pragma unroll
                for (int k1 = 0; k1 < 3; k1++) {
                    float Bacc[2];
#pragma unroll
                    for (int k2 = 0; k2 < 3; k2++) {
                        const float4 tq = shT[o * 27 + k0 * 9 + k1 * 3 + k2];
#pragma unroll
                        for (int el = 0; el < 2; el++) {
                            float D = fmaf(tq.z, S[el][3], fmaf(tq.y, C[el][3], tq.x));
                            if (k2 == 0)      Bacc[el] = D;
                            else if (k2 == 1) Bacc[el] = fmaf(C[el][2], D, Bacc[el]);
                            else              Bacc[el] = fmaf(S[el][2], D, Bacc[el]);
                        }
                    }
#pragma unroll
                    for (int el = 0; el < 2; el++) {
                        if (k1 == 0)      Aacc[el] = Bacc[el];
                        else if (k1 == 1) Aacc[el] = fmaf(C[el][1], Bacc[el], Aacc[el]);
                        else              Aacc[el] = fmaf(S[el][1], Bacc[el], Aacc[el]);
                    }
                }
#pragma unroll
                for (int el = 0; el < 2; el++) {
                    if (k0 == 0)      acc[el] = Aacc[el];
                    else if (k0 == 1) acc[el] = fmaf(C[el][0], Aacc[el], acc[el]);
                    else              acc[el] = fmaf(S[el][0], Aacc[el], acc[el]);
                }
            }
#pragma unroll
            for (int el = 0; el < 2; el++) outv[el][o] = acc[el];
        }

        float4* __restrict__ o4 = (float4*)out;
#pragma unroll
        for (int el = 0; el < 2; el++) {
            long long ei = e0 + el;
            if (ei < B) o4[ei] = make_float4(outv[el][0], outv[el][1], outv[el][2], outv[el][3]);
        }
    }
}

// ---------------------------------------------------------------------------
extern "C" void kernel_launch(void* const* d_in, const int* in_sizes, int n_in,
                              void* d_out, int out_size) {
    const float* xp = (const float*)d_in[0];
    const float* wp = (const float*)d_in[1];
    int sx = in_sizes[0];
    if (n_in >= 2 && in_sizes[0] == 12 && in_sizes[1] != 12) {
        xp = (const float*)d_in[1];
        wp = (const float*)d_in[0];
        sx = in_sizes[1];
    }
    const int B = sx / 4;

    build_T_kernel<<<1, 512>>>(wp);

    const int elems_per_block = 256 * 2;
    const int grid = (B + elems_per_block - 1) / elems_per_block;

    // PDL: qlayer's blocks may launch while build_T drains; the in-kernel
    // cudaGridDependencySynchronize() gates the T read.
    cudaLaunchConfig_t cfg = {};
    cfg.gridDim = dim3((unsigned)grid);
    cfg.blockDim = dim3(256);
    cfg.dynamicSmemBytes = 0;
    cfg.stream = 0;
    cudaLaunchAttribute attr[1];
    attr[0].id = cudaLaunchAttributeProgrammaticStreamSerialization;
    attr[0].val.programmaticStreamSerializationAllowed = 1;
    cfg.attrs = attr;
    cfg.numAttrs = 1;
    cudaError_t err = cudaLaunchKernelEx(&cfg, qlayer_kernel, xp, (float*)d_out, B);
    if (err != cudaSuccess) {
        // Fallback: plain launch (still correct; sync becomes a no-op).
        qlayer_kernel<<<grid, 256>>>(xp, (float*)d_out, B);
    }
}